// round 3
// baseline (speedup 1.0000x reference)
#include <cuda_runtime.h>
#include <cstddef>

#define NSPEC 10
#define KCH   64
#define D     9
#define NA1   3
#define NA2   8
#define NA3   18
#define ATOT  29
#define NEK   (NSPEC * KCH)   // 640 (species, channel) combos
#define NM    220             // C(12,3): monomials i<=j<=l over 10 vars (v9 == 1)
#define ROWF  12              // padded floats per monomial row (9 outputs + 3 pad)

// Scratch (device globals — allocation-free per harness rules)
__device__ float g_wp[NSPEC * ATOT * KCH];        // wp[z][b][k]
__device__ float g_S[(size_t)NEK * NM * ROWF];    // S[ek][m][o] symmetrized coeffs

// ---------------------------------------------------------------------------
// packed f32x2 helpers (sm_103a FFMA2 — PTX only)
// ---------------------------------------------------------------------------
__device__ __forceinline__ void ffma2(unsigned long long& d,
                                      unsigned long long a,
                                      unsigned long long b) {
    asm("fma.rn.f32x2 %0, %1, %2, %0;" : "+l"(d) : "l"(a), "l"(b));
}
__device__ __forceinline__ unsigned long long dup_f32(float t) {
    unsigned long long r;
    asm("mov.b64 %0, {%1, %1};" : "=l"(r) : "r"(__float_as_uint(t)));
    return r;
}
__device__ __forceinline__ void unpack2(unsigned long long p, float& lo, float& hi) {
    unsigned a, b;
    asm("mov.b64 {%0, %1}, %2;" : "=r"(a), "=r"(b) : "l"(p));
    lo = __uint_as_float(a); hi = __uint_as_float(b);
}

// ---------------------------------------------------------------------------
// Kernel A: wp[z][b][k] = sum_a w[z][a][k] * proj[a][b]
// ---------------------------------------------------------------------------
__global__ void wp_kernel(const float* __restrict__ w,
                          const float* __restrict__ proj) {
    int tid = blockIdx.x * blockDim.x + threadIdx.x;
    if (tid >= NSPEC * ATOT * KCH) return;
    int k = tid % KCH;
    int b = (tid / KCH) % ATOT;
    int z = tid / (KCH * ATOT);
    float s = 0.f;
#pragma unroll
    for (int a = 0; a < ATOT; a++)
        s = fmaf(w[(z * ATOT + a) * KCH + k], proj[a * ATOT + b], s);
    g_wp[tid] = s;
}

// ---------------------------------------------------------------------------
// Kernel B: symmetrized coefficients. One block per monomial m (220 blocks),
// 640 threads = (e,k).  UsT[b][o] (transposed, padded to 12) in smem, then
//   S[ek][m][o] = sum_b UsT[b][o] * wp[e, aoff+b, k]
// ---------------------------------------------------------------------------
__global__ void __launch_bounds__(NEK)
coeff_kernel(const float* __restrict__ U1,
             const float* __restrict__ U2,
             const float* __restrict__ U3) {
    const int m = blockIdx.x;
    int mi = 9, mj = 9, ml = 9;
    {
        int c = 0;
        for (int i = 0; i < 10; i++)
            for (int j = i; j < 10; j++)
                for (int l = j; l < 10; l++) {
                    if (c == m) { mi = i; mj = j; ml = l; }
                    c++;
                }
    }
    const int deg  = (ml < 9) ? 3 : (mj < 9) ? 2 : (mi < 9) ? 1 : 0;
    const int aoff = (deg == 3) ? (NA1 + NA2) : (deg == 2) ? NA1 : 0;
    const int acnt = (deg == 3) ? NA3 : (deg == 2) ? NA2 : (deg == 1) ? NA1 : 0;

    __shared__ __align__(16) float UsT[NA3 * 12];   // [b][o], padded

    const int t = threadIdx.x;
    if (t < NA3 * 12) UsT[t] = 0.f;
    __syncthreads();

    if (t < 9 * NA3) {
        int o = t / NA3, a = t % NA3;
        float s = 0.f;
        if (deg == 3) {
            int P[6][3] = {{mi,mj,ml},{mi,ml,mj},{mj,mi,ml},
                           {mj,ml,mi},{ml,mi,mj},{ml,mj,mi}};
#pragma unroll
            for (int p = 0; p < 6; p++) {
                bool dup = false;
#pragma unroll
                for (int q = 0; q < 6; q++)
                    if (q < p && P[q][0] == P[p][0] && P[q][1] == P[p][1] &&
                        P[q][2] == P[p][2]) dup = true;
                if (!dup)
                    s += U3[((((size_t)o * 9 + P[p][0]) * 9 + P[p][1]) * 9 + P[p][2]) * NA3 + a];
            }
        } else if (deg == 2 && a < NA2) {
            s = U2[(((size_t)o * 9 + mi) * 9 + mj) * NA2 + a];
            if (mi != mj)
                s += U2[(((size_t)o * 9 + mj) * 9 + mi) * NA2 + a];
        } else if (deg == 1 && a < NA1) {
            s = U1[((size_t)o * 9 + mi) * NA1 + a];
        }
        UsT[a * 12 + o] = s;
    }
    __syncthreads();

    const int e = t >> 6, k = t & 63;

    unsigned long long a01 = 0, a23 = 0, a45 = 0, a67 = 0;
    float a8 = 0.f;
    for (int b = 0; b < acnt; b++) {
        float wpb = g_wp[(e * ATOT + aoff + b) * KCH + k];
        const float* row = UsT + b * 12;
        ulonglong2 cA = *(const ulonglong2*)row;
        float c8 = row[8];
        unsigned long long wv = dup_f32(wpb);
        ffma2(a01, cA.x, wv);
        ffma2(a23, cA.y, wv);
        ulonglong2 cB = *(const ulonglong2*)(row + 4);
        ffma2(a45, cB.x, wv);
        ffma2(a67, cB.y, wv);
        a8 = fmaf(c8, wpb, a8);
    }

    float c9[9];
    unpack2(a01, c9[0], c9[1]);
    unpack2(a23, c9[2], c9[3]);
    unpack2(a45, c9[4], c9[5]);
    unpack2(a67, c9[6], c9[7]);
    c9[8] = a8;

    float* dst = g_S + ((size_t)t * NM + m) * ROWF;
    ((float4*)dst)[0] = make_float4(c9[0], c9[1], c9[2], c9[3]);
    ((float4*)dst)[1] = make_float4(c9[4], c9[5], c9[6], c9[7]);
    dst[8] = c9[8];
}

// ---------------------------------------------------------------------------
// Kernel C: evaluate. One block per (k, e), 64 threads; each thread handles
// atoms n0 = tid and n1 = tid + 64 of this species (n1 may be invalid ->
// recompute n0, suppress store). Coefficient row loaded once per monomial,
// applied to both atoms.
// ---------------------------------------------------------------------------
__global__ void __launch_bounds__(64)
eval_kernel(const float* __restrict__ x,
            const int* __restrict__ counts,
            float* __restrict__ out) {
    const int k = blockIdx.x;
    const int e = blockIdx.y;
    const int ek = e * KCH + k;

    __shared__ __align__(16) float Cs[NM * ROWF];
    {
        const float4* src = (const float4*)(g_S + (size_t)ek * NM * ROWF);
        float4* dst = (float4*)Cs;
        for (int t = threadIdx.x; t < NM * ROWF / 4; t += blockDim.x)
            dst[t] = src[t];
    }

    int start = 0, cnt = 0;
#pragma unroll
    for (int t = 0; t < NSPEC; t++) {
        int c = counts[t];
        if (t < e) start += c;
        if (t == e) cnt = c;
    }
    __syncthreads();

    const int tid = threadIdx.x;
    const int n0 = start + tid;                       // tid < 64 <= cnt always
    const bool has1 = (tid + 64) < cnt;
    const int n1 = has1 ? (n0 + 64) : n0;

    const float* xp0 = x + ((size_t)n0 * KCH + k) * D;
    const float* xp1 = x + ((size_t)n1 * KCH + k) * D;
    float v0[10], v1[10];
#pragma unroll
    for (int t = 0; t < 9; t++) { v0[t] = xp0[t]; v1[t] = xp1[t]; }
    v0[9] = 1.f; v1[9] = 1.f;

    unsigned long long b01 = 0, b23 = 0, b45 = 0, b67 = 0;  // atom n0, o0..7
    unsigned long long c01 = 0, c23 = 0, c45 = 0, c67 = 0;  // atom n1, o0..7
    float b8 = 0.f, c8s = 0.f;

    int m = 0;
#pragma unroll
    for (int i = 0; i < 10; i++) {
#pragma unroll
        for (int j = i; j < 10; j++) {
            float pij0 = v0[i] * v0[j];
            float pij1 = v1[i] * v1[j];
#pragma unroll
            for (int l = j; l < 10; l++) {
                float tm0 = pij0 * v0[l];
                float tm1 = pij1 * v1[l];
                const float* row = Cs + m * ROWF;
                ulonglong2 cA = *(const ulonglong2*)row;        // o0..3
                ulonglong2 cB = *(const ulonglong2*)(row + 4);  // o4..7
                float c8 = row[8];
                unsigned long long t0 = dup_f32(tm0);
                unsigned long long t1 = dup_f32(tm1);
                ffma2(b01, cA.x, t0);
                ffma2(b23, cA.y, t0);
                ffma2(b45, cB.x, t0);
                ffma2(b67, cB.y, t0);
                b8 = fmaf(c8, tm0, b8);
                ffma2(c01, cA.x, t1);
                ffma2(c23, cA.y, t1);
                ffma2(c45, cB.x, t1);
                ffma2(c67, cB.y, t1);
                c8s = fmaf(c8, tm1, c8s);
                m++;
            }
        }
    }

    float r[9];
    unpack2(b01, r[0], r[1]);
    unpack2(b23, r[2], r[3]);
    unpack2(b45, r[4], r[5]);
    unpack2(b67, r[6], r[7]);
    r[8] = b8;
    float* op0 = out + ((size_t)n0 * KCH + k) * D;
#pragma unroll
    for (int o = 0; o < 9; o++) op0[o] = r[o];

    if (has1) {
        unpack2(c01, r[0], r[1]);
        unpack2(c23, r[2], r[3]);
        unpack2(c45, r[4], r[5]);
        unpack2(c67, r[6], r[7]);
        r[8] = c8s;
        float* op1 = out + ((size_t)n1 * KCH + k) * D;
#pragma unroll
        for (int o = 0; o < 9; o++) op1[o] = r[o];
    }
}

// ---------------------------------------------------------------------------
extern "C" void kernel_launch(void* const* d_in, const int* in_sizes, int n_in,
                              void* d_out, int out_size) {
    const float* x      = (const float*)d_in[0];
    const int*   counts = (const int*)  d_in[1];
    const float* w      = (const float*)d_in[2];
    const float* proj   = (const float*)d_in[3];
    const float* U1     = (const float*)d_in[4];
    const float* U2     = (const float*)d_in[5];
    const float* U3     = (const float*)d_in[6];
    float* out = (float*)d_out;

    wp_kernel<<<(NSPEC * ATOT * KCH + 255) / 256, 256>>>(w, proj);
    coeff_kernel<<<NM, NEK>>>(U1, U2, U3);
    dim3 grid(KCH, NSPEC);
    eval_kernel<<<grid, 64>>>(x, counts, out);
}

// round 5
// speedup vs baseline: 1.6235x; 1.6235x over previous
#include <cuda_runtime.h>
#include <cstddef>

#define NSPEC 10
#define KCH   64
#define D     9
#define NA1   3
#define NA2   8
#define NA3   18
#define ATOT  29
#define NEK   (NSPEC * KCH)   // 640 (species, channel) combos
#define NM    220             // C(12,3): monomials i<=j<=l over 10 vars (v9 == 1)
#define ROWF  12              // padded floats per monomial row (9 outputs + 3 pad)
#define MSPLIT 110            // monomial split point for the 2-way eval split

// Scratch (device globals — allocation-free per harness rules)
__device__ float g_wp[NSPEC * ATOT * KCH];        // wp[z][b][k]
__device__ float g_S[(size_t)NEK * NM * ROWF];    // S[ek][m][o] symmetrized coeffs

// ---------------------------------------------------------------------------
// packed f32x2 helpers (sm_103a FFMA2 — PTX only)
// ---------------------------------------------------------------------------
__device__ __forceinline__ void ffma2(unsigned long long& d,
                                      unsigned long long a,
                                      unsigned long long b) {
    asm("fma.rn.f32x2 %0, %1, %2, %0;" : "+l"(d) : "l"(a), "l"(b));
}
__device__ __forceinline__ unsigned long long dup_f32(float t) {
    unsigned long long r;
    asm("mov.b64 %0, {%1, %1};" : "=l"(r) : "r"(__float_as_uint(t)));
    return r;
}
__device__ __forceinline__ void unpack2(unsigned long long p, float& lo, float& hi) {
    unsigned a, b;
    asm("mov.b64 {%0, %1}, %2;" : "=r"(a), "=r"(b) : "l"(p));
    lo = __uint_as_float(a); hi = __uint_as_float(b);
}

// ---------------------------------------------------------------------------
// Kernel A: wp[z][b][k] = sum_a w[z][a][k] * proj[a][b]
// ---------------------------------------------------------------------------
__global__ void wp_kernel(const float* __restrict__ w,
                          const float* __restrict__ proj) {
    int tid = blockIdx.x * blockDim.x + threadIdx.x;
    if (tid >= NSPEC * ATOT * KCH) return;
    int k = tid % KCH;
    int b = (tid / KCH) % ATOT;
    int z = tid / (KCH * ATOT);
    float s = 0.f;
#pragma unroll
    for (int a = 0; a < ATOT; a++)
        s = fmaf(w[(z * ATOT + a) * KCH + k], proj[a * ATOT + b], s);
    g_wp[tid] = s;
}

// ---------------------------------------------------------------------------
// Kernel B: symmetrized coefficients. One block per monomial m (220 blocks),
// 640 threads = (e,k).  UsT[b][o] (transposed, padded to 12) in smem, then
//   S[ek][m][o] = sum_b UsT[b][o] * wp[e, aoff+b, k]
// ---------------------------------------------------------------------------
__global__ void __launch_bounds__(NEK)
coeff_kernel(const float* __restrict__ U1,
             const float* __restrict__ U2,
             const float* __restrict__ U3) {
    const int m = blockIdx.x;
    int mi = 9, mj = 9, ml = 9;
    {
        int c = 0;
        for (int i = 0; i < 10; i++)
            for (int j = i; j < 10; j++)
                for (int l = j; l < 10; l++) {
                    if (c == m) { mi = i; mj = j; ml = l; }
                    c++;
                }
    }
    const int deg  = (ml < 9) ? 3 : (mj < 9) ? 2 : (mi < 9) ? 1 : 0;
    const int aoff = (deg == 3) ? (NA1 + NA2) : (deg == 2) ? NA1 : 0;
    const int acnt = (deg == 3) ? NA3 : (deg == 2) ? NA2 : (deg == 1) ? NA1 : 0;

    __shared__ __align__(16) float UsT[NA3 * 12];   // [b][o], padded

    const int t = threadIdx.x;
    if (t < NA3 * 12) UsT[t] = 0.f;
    __syncthreads();

    if (t < 9 * NA3) {
        int o = t / NA3, a = t % NA3;
        float s = 0.f;
        if (deg == 3) {
            int P[6][3] = {{mi,mj,ml},{mi,ml,mj},{mj,mi,ml},
                           {mj,ml,mi},{ml,mi,mj},{ml,mj,mi}};
#pragma unroll
            for (int p = 0; p < 6; p++) {
                bool dup = false;
#pragma unroll
                for (int q = 0; q < 6; q++)
                    if (q < p && P[q][0] == P[p][0] && P[q][1] == P[p][1] &&
                        P[q][2] == P[p][2]) dup = true;
                if (!dup)
                    s += U3[((((size_t)o * 9 + P[p][0]) * 9 + P[p][1]) * 9 + P[p][2]) * NA3 + a];
            }
        } else if (deg == 2 && a < NA2) {
            s = U2[(((size_t)o * 9 + mi) * 9 + mj) * NA2 + a];
            if (mi != mj)
                s += U2[(((size_t)o * 9 + mj) * 9 + mi) * NA2 + a];
        } else if (deg == 1 && a < NA1) {
            s = U1[((size_t)o * 9 + mi) * NA1 + a];
        }
        UsT[a * 12 + o] = s;
    }
    __syncthreads();

    const int e = t >> 6, k = t & 63;

    unsigned long long a01 = 0, a23 = 0, a45 = 0, a67 = 0;
    float a8 = 0.f;
    for (int b = 0; b < acnt; b++) {
        float wpb = g_wp[(e * ATOT + aoff + b) * KCH + k];
        const float* row = UsT + b * 12;
        ulonglong2 cA = *(const ulonglong2*)row;
        float c8 = row[8];
        unsigned long long wv = dup_f32(wpb);
        ffma2(a01, cA.x, wv);
        ffma2(a23, cA.y, wv);
        ulonglong2 cB = *(const ulonglong2*)(row + 4);
        ffma2(a45, cB.x, wv);
        ffma2(a67, cB.y, wv);
        a8 = fmaf(c8, wpb, a8);
    }

    float c9[9];
    unpack2(a01, c9[0], c9[1]);
    unpack2(a23, c9[2], c9[3]);
    unpack2(a45, c9[4], c9[5]);
    unpack2(a67, c9[6], c9[7]);
    c9[8] = a8;

    float* dst = g_S + ((size_t)t * NM + m) * ROWF;
    ((float4*)dst)[0] = make_float4(c9[0], c9[1], c9[2], c9[3]);
    ((float4*)dst)[1] = make_float4(c9[4], c9[5], c9[6], c9[7]);
    dst[8] = c9[8];
}

// ---------------------------------------------------------------------------
// Eval inner body: accumulate monomials m in [MS, ME) into r[9].
// Fully unrolled; the range guard folds at compile time (m is unroll-const).
// ---------------------------------------------------------------------------
template <int MS, int ME>
__device__ __forceinline__ void eval_range(const float* __restrict__ Cs,
                                           const float v[10], float r[9]) {
    unsigned long long a01 = 0, a23 = 0, a45 = 0, a67 = 0;
    float a8 = 0.f;
    int m = 0;
#pragma unroll
    for (int i = 0; i < 10; i++) {
#pragma unroll
        for (int j = i; j < 10; j++) {
            float pij = v[i] * v[j];
#pragma unroll
            for (int l = j; l < 10; l++) {
                if (m >= MS && m < ME) {
                    float tm = pij * v[l];
                    const float* row = Cs + m * ROWF;
                    ulonglong2 cA = *(const ulonglong2*)row;        // o0..3
                    ulonglong2 cB = *(const ulonglong2*)(row + 4);  // o4..7
                    float c8 = row[8];
                    unsigned long long tt = dup_f32(tm);
                    ffma2(a01, cA.x, tt);
                    ffma2(a23, cA.y, tt);
                    ffma2(a45, cB.x, tt);
                    ffma2(a67, cB.y, tt);
                    a8 = fmaf(c8, tm, a8);
                }
                m++;
            }
        }
    }
    unpack2(a01, r[0], r[1]);
    unpack2(a23, r[2], r[3]);
    unpack2(a45, r[4], r[5]);
    unpack2(a67, r[6], r[7]);
    r[8] = a8;
}

// ---------------------------------------------------------------------------
// Kernel C: evaluate. One block per (k, e), 256 threads.
//   atom = tid & 127 (one n of this species), half = tid >> 7.
//   half 0 sums monomials [0,110), half 1 sums [110,220); smem reduction.
// ---------------------------------------------------------------------------
__global__ void __launch_bounds__(256)
eval_kernel(const float* __restrict__ x,
            const int* __restrict__ counts,
            float* __restrict__ out) {
    const int k = blockIdx.x;
    const int e = blockIdx.y;
    const int ek = e * KCH + k;

    __shared__ __align__(16) float Cs[NM * ROWF];
    __shared__ float Red[128 * ROWF];
    {
        const float4* src = (const float4*)(g_S + (size_t)ek * NM * ROWF);
        float4* dst = (float4*)Cs;
        for (int t = threadIdx.x; t < NM * ROWF / 4; t += blockDim.x)
            dst[t] = src[t];
    }

    int start = 0, cnt = 0;
#pragma unroll
    for (int t = 0; t < NSPEC; t++) {
        int c = counts[t];
        if (t < e) start += c;
        if (t == e) cnt = c;
    }
    __syncthreads();

    const int tid  = threadIdx.x;
    const int atom = tid & 127;
    const int half = tid >> 7;
    const bool valid = atom < cnt;
    const int n = start + (valid ? atom : 0);

    const float* xp = x + ((size_t)n * KCH + k) * D;
    float v[10];
#pragma unroll
    for (int t = 0; t < 9; t++) v[t] = xp[t];
    v[9] = 1.f;

    float r[9];
    if (half == 0)
        eval_range<0, MSPLIT>(Cs, v, r);
    else
        eval_range<MSPLIT, NM>(Cs, v, r);

    if (half == 1) {
        float* rr = Red + atom * ROWF;
#pragma unroll
        for (int o = 0; o < 9; o++) rr[o] = r[o];
    }
    __syncthreads();

    if (half == 0 && valid) {
        const float* rr = Red + atom * ROWF;
        float* op = out + ((size_t)n * KCH + k) * D;
#pragma unroll
        for (int o = 0; o < 9; o++) op[o] = r[o] + rr[o];
    }
}

// ---------------------------------------------------------------------------
extern "C" void kernel_launch(void* const* d_in, const int* in_sizes, int n_in,
                              void* d_out, int out_size) {
    const float* x      = (const float*)d_in[0];
    const int*   counts = (const int*)  d_in[1];
    const float* w      = (const float*)d_in[2];
    const float* proj   = (const float*)d_in[3];
    const float* U1     = (const float*)d_in[4];
    const float* U2     = (const float*)d_in[5];
    const float* U3     = (const float*)d_in[6];
    float* out = (float*)d_out;

    wp_kernel<<<(NSPEC * ATOT * KCH + 255) / 256, 256>>>(w, proj);
    coeff_kernel<<<NM, NEK>>>(U1, U2, U3);
    dim3 grid(KCH, NSPEC);
    eval_kernel<<<grid, 256>>>(x, counts, out);
}